// round 4
// baseline (speedup 1.0000x reference)
#include <cuda_runtime.h>

#define NN   50000
#define NSEG 150000          // 3 relations x NN node-segments, v = r*NN + node
#define NT   256
#define EMAX 4500000
#define SCAN_BS 1024

// ---------------- scratch (static device globals; no allocs) ----------------
__device__ int   g_is64;
__device__ int   g_dout[NSEG];           // out-degree per (r,node)
__device__ int   g_din [NSEG];           // in-degree per (r,node)
__device__ int2  g_edges[EMAX];          // compact (src seg id, dst seg id)
__device__ int   g_off [NSEG + 1];       // CSR offsets by dst segment
__device__ int   g_cur [NSEG];           // fill cursors
__device__ int   g_csr [EMAX];           // src seg id per CSR slot
__device__ int   g_part[256];            // scan block partials (147 used)
__device__ float g_h1  [NSEG * 16];      // rsqrt(dout)-scaled layer-1 features
__device__ float g_m   [NSEG * 16];      // gathered+normalized messages
__device__ float g_s   [NSEG];           // scalar layer-2 messages
__device__ float g_o2  [NSEG];           // scalar gathered layer-2

// ---------------- dtype detection ----------------
__global__ void k_detect(const unsigned* __restrict__ p, int n) {
    __shared__ int found;
    if (threadIdx.x == 0) found = 0;
    __syncthreads();
    int f = 0;
    for (int i = threadIdx.x; i < n; i += blockDim.x)
        if (p[2 * i + 1] != 0u) f = 1;
    if (f) atomicOr(&found, 1);
    __syncthreads();
    if (threadIdx.x == 0) g_is64 = found ? 0 : 1;
}

__device__ __forceinline__ int ldidx(const void* __restrict__ p, int i) {
    return g_is64 ? (int)__ldg((const long long*)p + i)
                  : __ldg((const int*)p + i);
}

__device__ __forceinline__ float rs_of(int cnt) {
    return rsqrtf((float)(cnt > 0 ? cnt : 1));
}

// ---------------- zero degree counters ----------------
__global__ void k_zero() {
    int i = blockIdx.x * blockDim.x + threadIdx.x;
    if (i < NSEG) { g_dout[i] = 0; g_din[i] = 0; }
}

// ---------------- degrees + index compaction ----------------
__global__ void k_degc(const void* __restrict__ src, const void* __restrict__ dst,
                       int E, int r, int eoff) {
    int e = blockIdx.x * blockDim.x + threadIdx.x;
    if (e >= E) return;
    int s = r * NN + ldidx(src, e);
    int d = r * NN + ldidx(dst, e);
    atomicAdd(&g_dout[s], 1);
    atomicAdd(&g_din [d], 1);
    g_edges[eoff + e] = make_int2(s, d);
}

// ---------------- exclusive scan over g_din (3 kernels) ----------------
__global__ void k_scan1() {            // block partial sums
    __shared__ int ws[32];
    int b = blockIdx.x, t = threadIdx.x;
    int v = b * SCAN_BS + t;
    int val = (v < NSEG) ? g_din[v] : 0;
    #pragma unroll
    for (int o = 16; o; o >>= 1) val += __shfl_down_sync(0xffffffffu, val, o);
    if ((t & 31) == 0) ws[t >> 5] = val;
    __syncthreads();
    if (t < 32) {
        int x = ws[t];
        #pragma unroll
        for (int o = 16; o; o >>= 1) x += __shfl_down_sync(0xffffffffu, x, o);
        if (t == 0) g_part[b] = x;
    }
}

__global__ void k_scan2(int nblk) {    // exclusive scan of partials (nblk<=256)
    __shared__ int sh[256];
    int t = threadIdx.x;
    sh[t] = (t < nblk) ? g_part[t] : 0;
    __syncthreads();
    for (int o = 1; o < 256; o <<= 1) {
        int y = (t >= o) ? sh[t - o] : 0;
        __syncthreads();
        sh[t] += y;
        __syncthreads();
    }
    if (t < nblk) g_part[t] = (t == 0) ? 0 : sh[t - 1];
    if (t == 0) g_off[NSEG] = sh[nblk - 1];
}

__global__ void k_scan3() {            // per-block scan + base, write off/cur
    __shared__ int ws[32];
    int b = blockIdx.x, t = threadIdx.x;
    int v = b * SCAN_BS + t;
    int lane = t & 31, wid = t >> 5;
    int val = (v < NSEG) ? g_din[v] : 0;
    int x = val;
    #pragma unroll
    for (int o = 1; o < 32; o <<= 1) {
        int y = __shfl_up_sync(0xffffffffu, x, o);
        if (lane >= o) x += y;
    }
    if (lane == 31) ws[wid] = x;
    __syncthreads();
    if (wid == 0) {
        int w = ws[lane];
        #pragma unroll
        for (int o = 1; o < 32; o <<= 1) {
            int y = __shfl_up_sync(0xffffffffu, w, o);
            if (lane >= o) w += y;
        }
        ws[lane] = w;
    }
    __syncthreads();
    int base = g_part[b] + (wid > 0 ? ws[wid - 1] : 0);
    int excl = base + x - val;
    if (v < NSEG) { g_off[v] = excl; g_cur[v] = excl; }
}

// ---------------- CSR fill ----------------
__global__ void k_fill(int Etot) {
    int e = blockIdx.x * blockDim.x + threadIdx.x;
    if (e >= Etot) return;
    int2 ed = __ldg((const int2*)&g_edges[e]);
    int pos = atomicAdd(&g_cur[ed.y], 1);
    g_csr[pos] = ed.x;
}

// ---------------- layer 1: per-node transform ----------------
__global__ void k_layer1_node(const float* __restrict__ x, const float* __restrict__ W1) {
    __shared__ float sW[3 * 32 * 16];
    for (int i = threadIdx.x; i < 1536; i += blockDim.x) sW[i] = W1[i];
    __syncthreads();
    int n = blockIdx.x * blockDim.x + threadIdx.x;
    if (n >= NN) return;
    float xv[32];
    #pragma unroll
    for (int j = 0; j < 8; j++) {
        float4 v = __ldg((const float4*)(x + (size_t)n * 32) + j);
        xv[4*j] = v.x; xv[4*j+1] = v.y; xv[4*j+2] = v.z; xv[4*j+3] = v.w;
    }
    #pragma unroll
    for (int r = 0; r < 3; r++) {
        float a = rs_of(g_dout[r * NN + n]);
        float y[16];
        #pragma unroll
        for (int f = 0; f < 16; f++) y[f] = 0.f;
        #pragma unroll
        for (int j = 0; j < 32; j++) {
            float xj = xv[j];
            #pragma unroll
            for (int f = 0; f < 16; f++)
                y[f] += xj * sW[r * 512 + j * 16 + f];
        }
        float* hp = &g_h1[(size_t)(r * NN + n) * 16];
        #pragma unroll
        for (int f = 0; f < 16; f += 4)
            *(float4*)(hp + f) = make_float4(a*y[f], a*y[f+1], a*y[f+2], a*y[f+3]);
    }
}

// ---- layer 1 aggregate: warp per dst segment, 4 lanes/edge, no atomics -----
__global__ void k_gather16() {
    int gw = (blockIdx.x * blockDim.x + threadIdx.x) >> 5;
    int lane = threadIdx.x & 31;
    if (gw >= NSEG) return;
    int start = __ldg(&g_off[gw]);
    int end   = __ldg(&g_off[gw + 1]);
    int sub = lane >> 2, c = lane & 3;
    float4 acc = make_float4(0.f, 0.f, 0.f, 0.f);
    for (int i = start + sub; i < end; i += 8) {
        int s = __ldg(&g_csr[i]);
        float4 v = __ldg((const float4*)&g_h1[(size_t)s * 16] + c);
        acc.x += v.x; acc.y += v.y; acc.z += v.z; acc.w += v.w;
    }
    #pragma unroll
    for (int o = 4; o <= 16; o <<= 1) {
        acc.x += __shfl_xor_sync(0xffffffffu, acc.x, o);
        acc.y += __shfl_xor_sync(0xffffffffu, acc.y, o);
        acc.z += __shfl_xor_sync(0xffffffffu, acc.z, o);
        acc.w += __shfl_xor_sync(0xffffffffu, acc.w, o);
    }
    if (lane < 4) {  // lane == c, sub == 0
        float ain = rs_of(__ldg(&g_din[gw]));
        *(float4*)&g_m[(size_t)gw * 16 + lane * 4] =
            make_float4(acc.x * ain, acc.y * ain, acc.z * ain, acc.w * ain);
    }
}

// ---------------- combine + relu + layer-2 node transform ----------------
__global__ void k_combine(const float* __restrict__ b1, const float* __restrict__ W2) {
    __shared__ float sW2[48], sb1[48];
    if (threadIdx.x < 48) {
        sW2[threadIdx.x] = W2[threadIdx.x];
        sb1[threadIdx.x] = b1[threadIdx.x];
    }
    __syncthreads();
    int n = blockIdx.x * blockDim.x + threadIdx.x;
    if (n >= NN) return;
    float acc[16];
    #pragma unroll
    for (int f = 0; f < 16; f++) acc[f] = 0.f;
    #pragma unroll
    for (int r = 0; r < 3; r++) {
        const float* mp = &g_m[(size_t)(r * NN + n) * 16];
        #pragma unroll
        for (int f = 0; f < 16; f += 4) {
            float4 v = *(const float4*)(mp + f);
            acc[f]   += v.x + sb1[r*16 + f];
            acc[f+1] += v.y + sb1[r*16 + f + 1];
            acc[f+2] += v.z + sb1[r*16 + f + 2];
            acc[f+3] += v.w + sb1[r*16 + f + 3];
        }
    }
    #pragma unroll
    for (int f = 0; f < 16; f++) acc[f] = fmaxf(acc[f], 0.f);
    #pragma unroll
    for (int r = 0; r < 3; r++) {
        float aout = rs_of(g_dout[r * NN + n]);
        float dot = 0.f;
        #pragma unroll
        for (int f = 0; f < 16; f++) dot += acc[f] * sW2[r*16 + f];
        g_s[r * NN + n] = aout * dot;
    }
}

// ---------------- layer 2 aggregate: warp per dst segment ----------------
__global__ void k_gather1() {
    int gw = (blockIdx.x * blockDim.x + threadIdx.x) >> 5;
    int lane = threadIdx.x & 31;
    if (gw >= NSEG) return;
    int start = __ldg(&g_off[gw]);
    int end   = __ldg(&g_off[gw + 1]);
    float acc = 0.f;
    for (int i = start + lane; i < end; i += 32)
        acc += __ldg(&g_s[__ldg(&g_csr[i])]);
    #pragma unroll
    for (int o = 16; o; o >>= 1) acc += __shfl_xor_sync(0xffffffffu, acc, o);
    if (lane == 0)
        g_o2[gw] = acc * rs_of(__ldg(&g_din[gw]));
}

// ---------------- final ----------------
__global__ void k_final(float* __restrict__ out, const float* __restrict__ b2) {
    int n = blockIdx.x * blockDim.x + threadIdx.x;
    if (n >= NN) return;
    float o = __ldg(b2) + __ldg(b2 + 1) + __ldg(b2 + 2);
    #pragma unroll
    for (int r = 0; r < 3; r++)
        o += g_o2[r * NN + n];
    out[n] = o;
}

// ---------------- host ----------------
extern "C" void kernel_launch(void* const* d_in, const int* in_sizes, int n_in,
                              void* d_out, int out_size) {
    const float* x  = (const float*)d_in[0];
    const void*  src[3] = { d_in[1], d_in[3], d_in[5] };
    const void*  dst[3] = { d_in[2], d_in[4], d_in[6] };
    int          E[3]   = { in_sizes[1], in_sizes[3], in_sizes[5] };
    const float* W1 = (const float*)d_in[7];
    const float* b1 = (const float*)d_in[8];
    const float* W2 = (const float*)d_in[9];
    const float* b2 = (const float*)d_in[10];
    float*       out = (float*)d_out;

    int Etot = E[0] + E[1] + E[2];
    if (Etot > EMAX) Etot = EMAX;

    int nprobe = E[0] < 2048 ? E[0] : 2048;
    k_detect<<<1, NT>>>((const unsigned*)d_in[1], nprobe);

    k_zero<<<(NSEG + NT - 1) / NT, NT>>>();
    int eoff = 0;
    for (int r = 0; r < 3; r++) {
        k_degc<<<(E[r] + NT - 1) / NT, NT>>>(src[r], dst[r], E[r], r, eoff);
        eoff += E[r];
    }

    int nblk = (NSEG + SCAN_BS - 1) / SCAN_BS;   // 147
    k_scan1<<<nblk, SCAN_BS>>>();
    k_scan2<<<1, 256>>>(nblk);
    k_scan3<<<nblk, SCAN_BS>>>();
    k_fill<<<(Etot + NT - 1) / NT, NT>>>(Etot);

    k_layer1_node<<<(NN + NT - 1) / NT, NT>>>(x, W1);

    long long thr16 = (long long)NSEG * 32;
    k_gather16<<<(int)((thr16 + NT - 1) / NT), NT>>>();

    k_combine<<<(NN + NT - 1) / NT, NT>>>(b1, W2);
    k_gather1<<<(int)((thr16 + NT - 1) / NT), NT>>>();

    k_final<<<(NN + NT - 1) / NT, NT>>>(out, b2);
}